// round 1
// baseline (speedup 1.0000x reference)
#include <cuda_runtime.h>
#include <math.h>

#define TSTEPS 64
#define NB     4096
#define NROWS  (NB*TSTEPS)

// Scratch: x2 activations laid out [t][b][64] for the scan, and LSTM outputs
// laid out [dir][b][t][64] (== head's [2B, T, H]).
__device__ float g_x2[(size_t)TSTEPS*NB*64];     // 64 MB
__device__ float g_h [(size_t)2*NB*TSTEPS*64];   // 128 MB

__device__ __forceinline__ float sigm(float x) {
    return __fdividef(1.f, 1.f + __expf(-x));
}
__device__ __forceinline__ float tanh_fast(float x) {
    // tanh via exp(-2|x|) in (0,1]: no overflow, ~1e-7 error
    float a = fabsf(x);
    float e = __expf(-2.f * a);
    float t = __fdividef(1.f - e, 1.f + e);
    return copysignf(t, x);
}

// ---------------------------------------------------------------------------
// Trunk: per-thread row, W1/W2 in smem (broadcast reads), 64 reg accumulators.
// smem floats: W1s 8192 | W2s 6144 | prm 384 | shr 16640 (obs stage / x_s)
// ---------------------------------------------------------------------------
#define TRUNK_SMEM_F (8192 + 6144 + 384 + 16640)

__global__ __launch_bounds__(256) void trunk_kernel(
    const float* __restrict__ obs, const float* __restrict__ act,
    const float* __restrict__ W1, const float* __restrict__ b1,
    const float* __restrict__ g1, const float* __restrict__ be1,
    const float* __restrict__ W2, const float* __restrict__ b2,
    const float* __restrict__ g2, const float* __restrict__ be2)
{
    extern __shared__ float sm[];
    float* W1s = sm;              // [128][64]
    float* W2s = W1s + 8192;      // [96][64]
    float* prm = W2s + 6144;      // b1,g1,be1,b2,g2,be2
    float* shr = prm + 384;       // obs stage [256][33] then x_s [256][65]

    const int tid  = threadIdx.x;
    const int row0 = blockIdx.x * 256;
    const int row  = row0 + tid;

    for (int i = tid; i < 8192; i += 256) W1s[i] = W1[i];
    for (int i = tid; i < 6144; i += 256) W2s[i] = W2[i];
    if (tid < 64) {
        prm[tid]       = b1[tid];  prm[64 + tid]  = g1[tid];  prm[128 + tid] = be1[tid];
        prm[192 + tid] = b2[tid];  prm[256 + tid] = g2[tid];  prm[320 + tid] = be2[tid];
    }

    float acc[64];
    #pragma unroll
    for (int j = 0; j < 64; j++) acc[j] = 0.f;

    // Layer 1: obs[128] @ W1[128,64], k streamed in 4 chunks of 32 via smem
    for (int kc = 0; kc < 4; kc++) {
        __syncthreads();
        for (int i = tid; i < 256*32; i += 256) {
            int r = i >> 5, c = i & 31;
            shr[r*33 + c] = obs[(size_t)(row0 + r)*128 + kc*32 + c];
        }
        __syncthreads();
        #pragma unroll 4
        for (int k = 0; k < 32; k++) {
            float o = shr[tid*33 + k];
            const float4* w4 = (const float4*)&W1s[(kc*32 + k)*64];
            #pragma unroll
            for (int j4 = 0; j4 < 16; j4++) {
                float4 w = w4[j4];
                acc[4*j4+0] += o*w.x; acc[4*j4+1] += o*w.y;
                acc[4*j4+2] += o*w.z; acc[4*j4+3] += o*w.w;
            }
        }
    }

    // + b1, layernorm, relu -> x_s
    float m = 0.f;
    #pragma unroll
    for (int j = 0; j < 64; j++) { acc[j] += prm[j]; m += acc[j]; }
    m *= (1.f/64.f);
    float v = 0.f;
    #pragma unroll
    for (int j = 0; j < 64; j++) { float d = acc[j] - m; v += d*d; }
    v *= (1.f/64.f);
    float rs = rsqrtf(v + 1e-12f);
    __syncthreads();
    #pragma unroll
    for (int j = 0; j < 64; j++) {
        float x = (acc[j] - m)*rs*prm[64 + j] + prm[128 + j];
        shr[tid*65 + j] = fmaxf(x, 0.f);
    }
    __syncthreads();

    // Layer 2: [x(64), action(32)] @ W2[96,64]
    #pragma unroll
    for (int j = 0; j < 64; j++) acc[j] = 0.f;
    #pragma unroll 4
    for (int k = 0; k < 64; k++) {
        float o = shr[tid*65 + k];
        const float4* w4 = (const float4*)&W2s[k*64];
        #pragma unroll
        for (int j4 = 0; j4 < 16; j4++) {
            float4 w = w4[j4];
            acc[4*j4+0] += o*w.x; acc[4*j4+1] += o*w.y;
            acc[4*j4+2] += o*w.z; acc[4*j4+3] += o*w.w;
        }
    }
    const float* arow = act + (size_t)row*32;
    #pragma unroll 4
    for (int k = 0; k < 32; k++) {
        float a = __ldg(&arow[k]);
        const float4* w4 = (const float4*)&W2s[(64 + k)*64];
        #pragma unroll
        for (int j4 = 0; j4 < 16; j4++) {
            float4 w = w4[j4];
            acc[4*j4+0] += a*w.x; acc[4*j4+1] += a*w.y;
            acc[4*j4+2] += a*w.z; acc[4*j4+3] += a*w.w;
        }
    }

    // + b2, layernorm, relu -> g_x2[t][b][:]
    m = 0.f;
    #pragma unroll
    for (int j = 0; j < 64; j++) { acc[j] += prm[192 + j]; m += acc[j]; }
    m *= (1.f/64.f);
    v = 0.f;
    #pragma unroll
    for (int j = 0; j < 64; j++) { float d = acc[j] - m; v += d*d; }
    v *= (1.f/64.f);
    rs = rsqrtf(v + 1e-12f);

    const int b = row >> 6, t = row & 63;
    float4* dst = (float4*)&g_x2[((size_t)t*NB + b)*64];
    #pragma unroll
    for (int j4 = 0; j4 < 16; j4++) {
        float o0 = fmaxf((acc[4*j4+0]-m)*rs*prm[64+4*j4+0] + prm[128+4*j4+0], 0.f);
        float o1 = fmaxf((acc[4*j4+1]-m)*rs*prm[64+4*j4+1] + prm[128+4*j4+1], 0.f);
        float o2 = fmaxf((acc[4*j4+2]-m)*rs*prm[64+4*j4+2] + prm[128+4*j4+2], 0.f);
        float o3 = fmaxf((acc[4*j4+3]-m)*rs*prm[64+4*j4+3] + prm[128+4*j4+3], 0.f);
        dst[j4] = make_float4(o0, o1, o2, o3);
    }
}

// ---------------------------------------------------------------------------
// LSTM: persistent block per (64 sequences, direction). No global sync needed.
// W re-laid-out in smem as Wt[k][n*4+g] so one unit's 4 gates form a float4.
// Per thread: 8 seq x (2 units x 4 gates) = 64 accumulators, K=128 per step.
// smem floats: Wt 32768 | xh 128*68 | bs 256
// ---------------------------------------------------------------------------
#define LSTM_SMEM_F (32768 + 128*68 + 256)

__global__ __launch_bounds__(256) void lstm_kernel(
    const float* __restrict__ Wf, const float* __restrict__ bf,
    const float* __restrict__ Wb, const float* __restrict__ bbv)
{
    extern __shared__ float sm[];
    float* Wt = sm;                   // [128][256] re-laid-out
    float* xh = Wt + 32768;           // [128][68]: rows 0..63 = x_t, 64..127 = h
    float* bs = xh + 128*68;          // [256] re-laid-out bias

    const int tid = threadIdx.x;
    const int dir = blockIdx.y;
    const int b0  = blockIdx.x * 64;
    const float* W    = dir ? Wb  : Wf;
    const float* bias = dir ? bbv : bf;

    for (int i = tid; i < 32768; i += 256) {
        int k = i >> 8, col = i & 255;
        int g = col >> 6, n = col & 63;
        Wt[k*256 + n*4 + g] = W[i];
    }
    if (tid < 256) {
        int g = tid >> 6, n = tid & 63;
        bs[n*4 + g] = bias[tid];
    }
    for (int i = tid; i < 64*68; i += 256) xh[64*68 + i] = 0.f;   // h0 = 0
    {
        int t0 = dir ? 63 : 0;
        for (int i = tid; i < 4096; i += 256) {
            int s = i >> 6, k = i & 63;
            xh[k*68 + s] = g_x2[((size_t)t0*NB + b0 + s)*64 + k];
        }
    }
    __syncthreads();

    const int tx = tid & 31, ty = tid >> 5;
    float c[8][2];
    #pragma unroll
    for (int si = 0; si < 8; si++) { c[si][0] = 0.f; c[si][1] = 0.f; }

    float bias_r[8];
    {
        float4 b0v = *(const float4*)&bs[tx*4];
        float4 b1v = *(const float4*)&bs[(tx + 32)*4];
        bias_r[0]=b0v.x; bias_r[1]=b0v.y; bias_r[2]=b0v.z; bias_r[3]=b0v.w;
        bias_r[4]=b1v.x; bias_r[5]=b1v.y; bias_r[6]=b1v.z; bias_r[7]=b1v.w;
    }

    for (int st = 0; st < 64; st++) {
        const int t_eff = dir ? (63 - st) : st;

        float acc[8][8];
        #pragma unroll
        for (int si = 0; si < 8; si++)
            #pragma unroll
            for (int cj = 0; cj < 8; cj++) acc[si][cj] = 0.f;

        #pragma unroll 2
        for (int k = 0; k < 128; k++) {
            float4 w0 = *(const float4*)&Wt[k*256 + tx*4];
            float4 w1 = *(const float4*)&Wt[k*256 + 128 + tx*4];
            float4 a0 = *(const float4*)&xh[k*68 + ty*8];
            float4 a1 = *(const float4*)&xh[k*68 + ty*8 + 4];
            float av[8] = {a0.x,a0.y,a0.z,a0.w, a1.x,a1.y,a1.z,a1.w};
            float wv[8] = {w0.x,w0.y,w0.z,w0.w, w1.x,w1.y,w1.z,w1.w};
            #pragma unroll
            for (int si = 0; si < 8; si++)
                #pragma unroll
                for (int cj = 0; cj < 8; cj++)
                    acc[si][cj] += av[si]*wv[cj];
        }
        __syncthreads();   // all K-loop reads of xh done

        #pragma unroll
        for (int si = 0; si < 8; si++) {
            const int s = ty*8 + si;
            #pragma unroll
            for (int nh = 0; nh < 2; nh++) {
                const int n = tx + nh*32;
                float zi = acc[si][nh*4+0] + bias_r[nh*4+0];
                float zj = acc[si][nh*4+1] + bias_r[nh*4+1];
                float zf = acc[si][nh*4+2] + bias_r[nh*4+2];
                float zo = acc[si][nh*4+3] + bias_r[nh*4+3];
                float ig = sigm(zi);
                float jg = tanh_fast(zj);
                float fg = sigm(zf + 1.f);        // forget_bias = 1.0
                float og = sigm(zo);
                float cc = c[si][nh]*fg + ig*jg;
                c[si][nh] = cc;
                float h = tanh_fast(cc)*og;
                xh[(64 + n)*68 + s] = h;
                g_h[(((size_t)dir*NB + b0 + s)*TSTEPS + t_eff)*64 + n] = h;
            }
        }

        if (st < 63) {
            const int tn = dir ? (63 - st - 1) : (st + 1);
            for (int i = tid; i < 4096; i += 256) {
                int s = i >> 6, k = i & 63;
                xh[k*68 + s] = g_x2[((size_t)tn*NB + b0 + s)*64 + k];
            }
        }
        __syncthreads();   // new h + next x visible
    }
}

// ---------------------------------------------------------------------------
// Head: one block (64 threads) per sequence q in [0, 2B).
// ---------------------------------------------------------------------------
__global__ __launch_bounds__(64) void head_kernel(
    const float* __restrict__ wx, const float* __restrict__ bx,
    const float* __restrict__ wp, const float* __restrict__ bp,
    const float* __restrict__ gp, const float* __restrict__ bep,
    const float* __restrict__ W3, const float* __restrict__ b3,
    float* __restrict__ out)
{
    __shared__ float h_s[64*65];
    __shared__ float wxs[64], wps[64];
    __shared__ float xs_s[64], sA[64], sB[64];

    const int t = threadIdx.x;
    const int q = blockIdx.x;
    const float* hrow = g_h + (size_t)q*4096;

    for (int i = t; i < 4096; i += 64) {
        int tt = i >> 6, n = i & 63;
        h_s[tt*65 + n] = hrow[i];
    }
    wxs[t] = wx[t]; wps[t] = wp[t];
    __syncthreads();

    float xv = 0.f, pv = 0.f;
    #pragma unroll 8
    for (int n = 0; n < 64; n++) {
        float hv = h_s[t*65 + n];
        xv += hv*wxs[n];
        pv += hv*wps[n];
    }
    xs_s[t] = xv + bx[0];
    sA[t]   = pv + bp[0];
    __syncthreads();

    // layernorm over T (redundant per-thread reduction: 64 broadcast reads)
    float m = 0.f;
    for (int i = 0; i < 64; i++) m += sA[i];
    m *= (1.f/64.f);
    float v = 0.f;
    for (int i = 0; i < 64; i++) { float d = sA[i] - m; v += d*d; }
    v *= (1.f/64.f);
    float rs = rsqrtf(v + 1e-12f);
    float pr = fmaxf((sA[t] - m)*rs*gp[t] + bep[t], 0.f);
    sB[t] = pr;
    __syncthreads();

    float l = b3[t];
    #pragma unroll 8
    for (int k = 0; k < 64; k++) l += sB[k]*W3[k*64 + t];
    __syncthreads();      // all reads of sA (ps) complete before overwrite
    sA[t] = l;
    __syncthreads();

    float mx = -1e30f;
    for (int i = 0; i < 64; i++) mx = fmaxf(mx, sA[i]);
    float den = 0.f, num = 0.f;
    for (int i = 0; i < 64; i++) {
        float e = __expf(sA[i] - mx);
        den += e;
        num += e*xs_s[i];
    }
    if (t == 0) out[q] = num / den;
}

// ---------------------------------------------------------------------------
extern "C" void kernel_launch(void* const* d_in, const int* in_sizes, int n_in,
                              void* d_out, int out_size)
{
    const float* obs  = (const float*)d_in[0];
    const float* act  = (const float*)d_in[1];
    const float* W1   = (const float*)d_in[2];
    const float* b1   = (const float*)d_in[3];
    const float* g1   = (const float*)d_in[4];
    const float* be1  = (const float*)d_in[5];
    const float* W2   = (const float*)d_in[6];
    const float* b2   = (const float*)d_in[7];
    const float* g2   = (const float*)d_in[8];
    const float* be2  = (const float*)d_in[9];
    const float* Wf   = (const float*)d_in[10];
    const float* bf   = (const float*)d_in[11];
    const float* Wb   = (const float*)d_in[12];
    const float* bb   = (const float*)d_in[13];
    const float* wx   = (const float*)d_in[14];
    const float* bx   = (const float*)d_in[15];
    const float* wp   = (const float*)d_in[16];
    const float* bp   = (const float*)d_in[17];
    const float* gp   = (const float*)d_in[18];
    const float* bep  = (const float*)d_in[19];
    const float* W3   = (const float*)d_in[20];
    const float* b3   = (const float*)d_in[21];

    const int trunk_smem = TRUNK_SMEM_F * 4;
    const int lstm_smem  = LSTM_SMEM_F * 4;
    cudaFuncSetAttribute(trunk_kernel, cudaFuncAttributeMaxDynamicSharedMemorySize, trunk_smem);
    cudaFuncSetAttribute(lstm_kernel,  cudaFuncAttributeMaxDynamicSharedMemorySize, lstm_smem);

    trunk_kernel<<<NROWS/256, 256, trunk_smem>>>(obs, act, W1, b1, g1, be1,
                                                 W2, b2, g2, be2);
    lstm_kernel<<<dim3(NB/64, 2), 256, lstm_smem>>>(Wf, bf, Wb, bb);
    head_kernel<<<2*NB, 64>>>(wx, bx, wp, bp, gp, bep, W3, b3, (float*)d_out);
}

// round 5
// speedup vs baseline: 1.2531x; 1.2531x over previous
#include <cuda_runtime.h>
#include <cuda_bf16.h>
#include <math.h>
#include <stdint.h>

#define TSTEPS 64
#define NB     4096
#define NROWS  (NB*TSTEPS)

// Scratch: x2 activations [t][b][64]; LSTM outputs [dir][b][t][64].
__device__ float g_x2[(size_t)TSTEPS*NB*64];     // 64 MB
__device__ float g_h [(size_t)2*NB*TSTEPS*64];   // 128 MB

__device__ __forceinline__ float sigm(float x) {
    return __fdividef(1.f, 1.f + __expf(-x));
}
__device__ __forceinline__ float tanh_fast(float x) {
    float a = fabsf(x);
    float e = __expf(-2.f * a);
    float t = __fdividef(1.f - e, 1.f + e);
    return copysignf(t, x);
}
__device__ __forceinline__ uint32_t smem_to_u32(const void* p) {
    uint32_t a;
    asm("{ .reg .u64 t; cvta.to.shared.u64 t, %1; cvt.u32.u64 %0, t; }"
        : "=r"(a) : "l"(p));
    return a;
}
__device__ __forceinline__ float bf16_round(float a) {
    return __bfloat162float(__float2bfloat16(a));
}
// pack (a -> low bf16, b -> high bf16)
__device__ __forceinline__ uint32_t pk2(float a, float b) {
    uint32_t r;
    asm("cvt.rn.bf16x2.f32 %0, %1, %2;" : "=r"(r) : "f"(b), "f"(a));
    return r;
}

#define LDSM_X4(r0, r1, r2, r3, addr) \
    asm volatile("ldmatrix.sync.aligned.m8n8.x4.shared.b16 {%0,%1,%2,%3}, [%4];" \
        : "=r"(r0), "=r"(r1), "=r"(r2), "=r"(r3) : "r"(addr))

#define MMA_BF16(d, a, b0v, b1v) \
    asm volatile("mma.sync.aligned.m16n8k16.row.col.f32.bf16.bf16.f32 " \
        "{%0,%1,%2,%3}, {%4,%5,%6,%7}, {%8,%9}, {%0,%1,%2,%3};" \
        : "+f"((d)[0]), "+f"((d)[1]), "+f"((d)[2]), "+f"((d)[3]) \
        : "r"((a)[0]), "r"((a)[1]), "r"((a)[2]), "r"((a)[3]), "r"(b0v), "r"(b1v))

// ---------------------------------------------------------------------------
// Trunk (IDENTICAL to round-1 passing version)
// ---------------------------------------------------------------------------
#define TRUNK_SMEM_F (8192 + 6144 + 384 + 16640)

__global__ __launch_bounds__(256) void trunk_kernel(
    const float* __restrict__ obs, const float* __restrict__ act,
    const float* __restrict__ W1, const float* __restrict__ b1,
    const float* __restrict__ g1, const float* __restrict__ be1,
    const float* __restrict__ W2, const float* __restrict__ b2,
    const float* __restrict__ g2, const float* __restrict__ be2)
{
    extern __shared__ float sm[];
    float* W1s = sm;
    float* W2s = W1s + 8192;
    float* prm = W2s + 6144;
    float* shr = prm + 384;

    const int tid  = threadIdx.x;
    const int row0 = blockIdx.x * 256;
    const int row  = row0 + tid;

    for (int i = tid; i < 8192; i += 256) W1s[i] = W1[i];
    for (int i = tid; i < 6144; i += 256) W2s[i] = W2[i];
    if (tid < 64) {
        prm[tid]       = b1[tid];  prm[64 + tid]  = g1[tid];  prm[128 + tid] = be1[tid];
        prm[192 + tid] = b2[tid];  prm[256 + tid] = g2[tid];  prm[320 + tid] = be2[tid];
    }

    float acc[64];
    #pragma unroll
    for (int j = 0; j < 64; j++) acc[j] = 0.f;

    for (int kc = 0; kc < 4; kc++) {
        __syncthreads();
        for (int i = tid; i < 256*32; i += 256) {
            int r = i >> 5, c = i & 31;
            shr[r*33 + c] = obs[(size_t)(row0 + r)*128 + kc*32 + c];
        }
        __syncthreads();
        #pragma unroll 4
        for (int k = 0; k < 32; k++) {
            float o = shr[tid*33 + k];
            const float4* w4 = (const float4*)&W1s[(kc*32 + k)*64];
            #pragma unroll
            for (int j4 = 0; j4 < 16; j4++) {
                float4 w = w4[j4];
                acc[4*j4+0] += o*w.x; acc[4*j4+1] += o*w.y;
                acc[4*j4+2] += o*w.z; acc[4*j4+3] += o*w.w;
            }
        }
    }

    float m = 0.f;
    #pragma unroll
    for (int j = 0; j < 64; j++) { acc[j] += prm[j]; m += acc[j]; }
    m *= (1.f/64.f);
    float v = 0.f;
    #pragma unroll
    for (int j = 0; j < 64; j++) { float d = acc[j] - m; v += d*d; }
    v *= (1.f/64.f);
    float rs = rsqrtf(v + 1e-12f);
    __syncthreads();
    #pragma unroll
    for (int j = 0; j < 64; j++) {
        float x = (acc[j] - m)*rs*prm[64 + j] + prm[128 + j];
        shr[tid*65 + j] = fmaxf(x, 0.f);
    }
    __syncthreads();

    #pragma unroll
    for (int j = 0; j < 64; j++) acc[j] = 0.f;
    #pragma unroll 4
    for (int k = 0; k < 64; k++) {
        float o = shr[tid*65 + k];
        const float4* w4 = (const float4*)&W2s[k*64];
        #pragma unroll
        for (int j4 = 0; j4 < 16; j4++) {
            float4 w = w4[j4];
            acc[4*j4+0] += o*w.x; acc[4*j4+1] += o*w.y;
            acc[4*j4+2] += o*w.z; acc[4*j4+3] += o*w.w;
        }
    }
    const float* arow = act + (size_t)row*32;
    #pragma unroll 4
    for (int k = 0; k < 32; k++) {
        float a = __ldg(&arow[k]);
        const float4* w4 = (const float4*)&W2s[(64 + k)*64];
        #pragma unroll
        for (int j4 = 0; j4 < 16; j4++) {
            float4 w = w4[j4];
            acc[4*j4+0] += a*w.x; acc[4*j4+1] += a*w.y;
            acc[4*j4+2] += a*w.z; acc[4*j4+3] += a*w.w;
        }
    }

    m = 0.f;
    #pragma unroll
    for (int j = 0; j < 64; j++) { acc[j] += prm[192 + j]; m += acc[j]; }
    m *= (1.f/64.f);
    v = 0.f;
    #pragma unroll
    for (int j = 0; j < 64; j++) { float d = acc[j] - m; v += d*d; }
    v *= (1.f/64.f);
    rs = rsqrtf(v + 1e-12f);

    const int b = row >> 6, t = row & 63;
    float4* dst = (float4*)&g_x2[((size_t)t*NB + b)*64];
    #pragma unroll
    for (int j4 = 0; j4 < 16; j4++) {
        float o0 = fmaxf((acc[4*j4+0]-m)*rs*prm[64+4*j4+0] + prm[128+4*j4+0], 0.f);
        float o1 = fmaxf((acc[4*j4+1]-m)*rs*prm[64+4*j4+1] + prm[128+4*j4+1], 0.f);
        float o2 = fmaxf((acc[4*j4+2]-m)*rs*prm[64+4*j4+2] + prm[128+4*j4+2], 0.f);
        float o3 = fmaxf((acc[4*j4+3]-m)*rs*prm[64+4*j4+3] + prm[128+4*j4+3], 0.f);
        dst[j4] = make_float4(o0, o1, o2, o3);
    }
}

// ---------------------------------------------------------------------------
// LSTM via mma.sync m16n8k16 bf16 (split hi/lo, 3 passes), fp32 accum.
// CTA = 64 sequences x 1 direction, 256 threads (8 warps), grid (64, 2).
//
//  A (activations) : [64 m][128 k] bf16 hi/lo in smem; k<64 = x_t, k>=64 = h.
//  B = W^T gate-interleaved: n' = u*4 + g, stored [256 n'][128 k] bf16 hi/lo.
//  Rows are 256B; swizzle: byte_in_row ^= (row&7)<<4  (conflict-free ldmatrix).
//  Warp (wm=wid>>1, wn=wid&1): M-tile wm*16, N-half wn*128 (16 n8-tiles).
//  Gate quads (i,j | f,o) of one unit live in lane pairs -> one shfl.xor(1).
// ---------------------------------------------------------------------------
#define SM_AHI   0
#define SM_ALO   16384
#define SM_BHI   32768
#define SM_BLO   98304
#define SM_BS    163840
#define SM_HBUF  164864
#define LSTM_SMEM_BYTES (SM_HBUF + 16384 + 256)

__global__ __launch_bounds__(256, 1) void lstm_mma_kernel(
    const float* __restrict__ Wf, const float* __restrict__ bf,
    const float* __restrict__ Wb, const float* __restrict__ bbv)
{
    extern __shared__ char smc[];
    const uint32_t sb = smem_to_u32(smc);
    float* bs   = (float*)(smc + SM_BS);
    float* hbuf = (float*)(smc + SM_HBUF);

    const int tid  = threadIdx.x;
    const int wid  = tid >> 5;
    const int lane = tid & 31;
    const int q    = lane & 3;
    const int lr   = lane >> 2;
    const int mi   = lane >> 3;
    const int wm   = wid >> 1;        // m-tile base wm*16
    const int wn   = wid & 1;         // n-half base wn*128

    const int dir = blockIdx.y;
    const int b0  = blockIdx.x * 64;
    const float* W    = dir ? Wb  : Wf;
    const float* bias = dir ? bbv : bf;

    // ---- B = W^T, gate-interleaved, split bf16 hi/lo, swizzled ----
    for (int i = tid; i < 128*256; i += 256) {
        int k = i >> 8, no = i & 255;
        int g = no >> 6, u = no & 63;
        int np = (u << 2) | g;
        float w  = W[i];
        float wh = bf16_round(w);
        uint32_t off = (uint32_t)np*256 + (((uint32_t)k*2) ^ ((np & 7) << 4));
        *(__nv_bfloat16*)(smc + SM_BHI + off) = __float2bfloat16(wh);
        *(__nv_bfloat16*)(smc + SM_BLO + off) = __float2bfloat16(w - wh);
    }
    {   // bias reorder
        int g = tid >> 6, u = tid & 63;
        bs[(u << 2) | g] = bias[tid];
    }
    // ---- zero all of A (hi+lo) ----
    {
        uint4 z = make_uint4(0,0,0,0);
        uint4* a4 = (uint4*)(smc + SM_AHI);
        for (int i = tid; i < 2048; i += 256) a4[i] = z;
    }
    __syncthreads();   // A zero done before x-region writes (disjoint bytes anyway)

    // ---- load x_{t0} into A x-region ----
    {
        const int t0 = dir ? 63 : 0;
        const int srow = tid >> 2, kq = (tid & 3) * 16;
        const float4* xp = (const float4*)(g_x2 + ((size_t)t0*NB + b0 + srow)*64 + kq);
        const uint32_t rowoff = (uint32_t)srow * 256;
        const uint32_t sw = (srow & 7) << 4;
        #pragma unroll
        for (int j4 = 0; j4 < 4; j4++) {
            float4 v = xp[j4];
            int k = kq + j4*4;
            float hx = bf16_round(v.x), hy = bf16_round(v.y);
            float hz = bf16_round(v.z), hw = bf16_round(v.w);
            *(uint32_t*)(smc + SM_AHI + rowoff + (((uint32_t)(2*k))   ^ sw)) = pk2(v.x, v.y);
            *(uint32_t*)(smc + SM_AHI + rowoff + (((uint32_t)(2*k+4)) ^ sw)) = pk2(v.z, v.w);
            *(uint32_t*)(smc + SM_ALO + rowoff + (((uint32_t)(2*k))   ^ sw)) = pk2(v.x - hx, v.y - hy);
            *(uint32_t*)(smc + SM_ALO + rowoff + (((uint32_t)(2*k+4)) ^ sw)) = pk2(v.z - hz, v.w - hw);
        }
    }

    // ---- ldmatrix lane-address components ----
    // A: matrices ordered (m0-7,k0-7),(m8-15,k0-7),(m0-7,k8-15),(m8-15,k8-15)
    const int a_row   = wm*16 + (lane & 7) + ((mi & 1) << 3);
    const uint32_t a_rowoff = (uint32_t)a_row * 256;
    const uint32_t a_sw     = (a_row & 7) << 4;
    const uint32_t a_kh     = (uint32_t)(mi >> 1) << 4;
    // B: matrices ordered (n0-7,k0-7),(n0-7,k8-15),(n8-15,k0-7),(n8-15,k8-15)
    const int b_rowc  = (lane & 7) + ((mi >> 1) << 3);       // 0..15 within pair
    const uint32_t b_rowoff = (uint32_t)(wn*128 + b_rowc) * 256;
    const uint32_t b_sw     = (b_rowc & 7) << 4;
    const uint32_t b_kh     = (uint32_t)(mi & 1) << 4;

    float c0s[16], c1s[16];
    #pragma unroll
    for (int t = 0; t < 16; t++) { c0s[t] = 0.f; c1s[t] = 0.f; }

    #pragma unroll 1
    for (int st = 0; st < 64; st++) {
        const int t_eff = dir ? (63 - st) : st;

        __syncthreads();   // A (x + h) ready

        float acc[16][4];
        #pragma unroll
        for (int t = 0; t < 16; t++)
            #pragma unroll
            for (int j = 0; j < 4; j++) acc[t][j] = 0.f;

        #pragma unroll 1
        for (int kc = 0; kc < 8; kc++) {
            const uint32_t kb = (uint32_t)kc * 32;
            uint32_t ahi[4], alo[4];
            LDSM_X4(ahi[0], ahi[1], ahi[2], ahi[3],
                    sb + SM_AHI + a_rowoff + ((kb + a_kh) ^ a_sw));
            LDSM_X4(alo[0], alo[1], alo[2], alo[3],
                    sb + SM_ALO + a_rowoff + ((kb + a_kh) ^ a_sw));
            const uint32_t bko = (kb + b_kh) ^ b_sw;
            #pragma unroll
            for (int p = 0; p < 8; p++) {
                uint32_t r0, r1, r2, r3;
                LDSM_X4(r0, r1, r2, r3,
                        sb + SM_BHI + b_rowoff + (uint32_t)p*4096 + bko);
                MMA_BF16(acc[2*p],   ahi, r0, r1);
                MMA_BF16(acc[2*p+1], ahi, r2, r3);
                MMA_BF16(acc[2*p],   alo, r0, r1);
                MMA_BF16(acc[2*p+1], alo, r2, r3);
            }
            #pragma unroll
            for (int p = 0; p < 8; p++) {
                uint32_t r0, r1, r2, r3;
                LDSM_X4(r0, r1, r2, r3,
                        sb + SM_BLO + b_rowoff + (uint32_t)p*4096 + bko);
                MMA_BF16(acc[2*p],   ahi, r0, r1);
                MMA_BF16(acc[2*p+1], ahi, r2, r3);
            }
        }

        __syncthreads();   // all reads of A done; safe to overwrite h / x

        // ---- epilogue ----
        const int m0 = wm*16 + lr, m1 = m0 + 8;
        #pragma unroll
        for (int t = 0; t < 16; t++) {
            const int ncol = wn*128 + t*8 + q*2;
            const float bias0 = bs[ncol], bias1 = bs[ncol + 1];
            float za0 = acc[t][0] + bias0, za1 = acc[t][1] + bias1;
            float zb0 = acc[t][2] + bias0, zb1 = acc[t][3] + bias1;
            float pa0 = __shfl_xor_sync(0xffffffffu, za0, 1);
            float pa1 = __shfl_xor_sync(0xffffffffu, za1, 1);
            float pb0 = __shfl_xor_sync(0xffffffffu, zb0, 1);
            float pb1 = __shfl_xor_sync(0xffffffffu, zb1, 1);
            float zi0, zj0, zf0, zo0, zi1, zj1, zf1, zo1;
            if (q & 1) { zi0 = pa0; zj0 = pa1; zf0 = za0; zo0 = za1;
                         zi1 = pb0; zj1 = pb1; zf1 = zb0; zo1 = zb1; }
            else       { zi0 = za0; zj0 = za1; zf0 = pa0; zo0 = pa1;
                         zi1 = zb0; zj1 = zb1; zf1 = pb0; zo1 = pb1; }

            float cc0 = c0s[t]*sigm(zf0 + 1.f) + sigm(zi0)*tanh_fast(zj0);
            float cc1 = c1s[t]*sigm(zf1 + 1.f) + sigm(zi1)*tanh_fast(zj1);
            c0s[t] = cc0;  c1s[t] = cc1;
            float h0 = tanh_fast(cc0)*sigm(zo0);
            float h1 = tanh_fast(cc1)*sigm(zo1);

            if (!(lane & 1)) {   // one writer per duplicate pair
                const int u = wn*32 + 2*t + (q >> 1);
                hbuf[m0*64 + u] = h0;
                hbuf[m1*64 + u] = h1;
                const uint32_t kb = 128 + 2*u;
                float h0h = bf16_round(h0), h1h = bf16_round(h1);
                *(__nv_bfloat16*)(smc + SM_AHI + m0*256 + (kb ^ ((m0 & 7) << 4))) = __float2bfloat16(h0h);
                *(__nv_bfloat16*)(smc + SM_AHI + m1*256 + (kb ^ ((m1 & 7) << 4))) = __float2bfloat16(h1h);
                *(__nv_bfloat16*)(smc + SM_ALO + m0*256 + (kb ^ ((m0 & 7) << 4))) = __float2bfloat16(h0 - h0h);
                *(__nv_bfloat16*)(smc + SM_ALO + m1*256 + (kb ^ ((m1 & 7) << 4))) = __float2bfloat16(h1 - h1h);
            }
        }

        // ---- prefetch x_{t+1} into A x-region (disjoint from h bytes) ----
        if (st < 63) {
            const int tn = dir ? (62 - st) : (st + 1);
            const int srow = tid >> 2, kq = (tid & 3) * 16;
            const float4* xp = (const float4*)(g_x2 + ((size_t)tn*NB + b0 + srow)*64 + kq);
            const uint32_t rowoff = (uint32_t)srow * 256;
            const uint32_t sw = (srow & 7) << 4;
            #pragma unroll
            for (int j4 = 0; j4 < 4; j4++) {
                float4 v = xp[j4];
                int k = kq + j4*4;
                float hx = bf16_round(v.x), hy = bf16_round(v.y);
                float hz = bf16_round(v.z), hw = bf16_round(v.w);
                *(uint32_t*)(smc + SM_AHI + rowoff + (((uint32_t)(2*k))   ^ sw)) = pk2(v.x, v.y);
                *(uint32_t*)(smc + SM_AHI + rowoff + (((uint32_t)(2*k+4)) ^ sw)) = pk2(v.z, v.w);
                *(uint32_t*)(smc + SM_ALO + rowoff + (((uint32_t)(2*k))   ^ sw)) = pk2(v.x - hx, v.y - hy);
                *(uint32_t*)(smc + SM_ALO + rowoff + (((uint32_t)(2*k+4)) ^ sw)) = pk2(v.z - hz, v.w - hw);
            }
        }

        __syncthreads();   // hbuf + A fully written

        // ---- coalesced h store: hbuf -> g_h[dir][b][t][64] ----
        {
            const int srow = tid >> 2, kq = (tid & 3) * 16;
            float4* dst = (float4*)(g_h + (((size_t)dir*NB + b0 + srow)*TSTEPS + t_eff)*64 + kq);
            const float4* src = (const float4*)(hbuf + srow*64 + kq);
            #pragma unroll
            for (int j4 = 0; j4 < 4; j4++) dst[j4] = src[j4];
        }
    }
}

// ---------------------------------------------------------------------------
// Head (IDENTICAL to round-1 passing version)
// ---------------------------------------------------------------------------
__global__ __launch_bounds__(64) void head_kernel(
    const float* __restrict__ wx, const float* __restrict__ bx,
    const float* __restrict__ wp, const float* __restrict__ bp,
    const float* __restrict__ gp, const float* __restrict__ bep,
    const float* __restrict__ W3, const float* __restrict__ b3,
    float* __restrict__ out)
{
    __shared__ float h_s[64*65];
    __shared__ float wxs[64], wps[64];
    __shared__ float xs_s[64], sA[64], sB[64];

    const int t = threadIdx.x;
    const int q = blockIdx.x;
    const float* hrow = g_h + (size_t)q*4096;

    for (int i = t; i < 4096; i += 64) {
        int tt = i >> 6, n = i & 63;
        h_s[tt*65 + n] = hrow[i];
    }
    wxs[t] = wx[t]; wps[t] = wp[t];
    __syncthreads();

    float xv = 0.f, pv = 0.f;
    #pragma unroll 8
    for (int n = 0; n < 64; n++) {
        float hv = h_s[t*65 + n];
        xv += hv*wxs[n];
        pv += hv*wps[n];
    }
    xs_s[t] = xv + bx[0];
    sA[t]   = pv + bp[0];
    __syncthreads();

    float m = 0.f;
    for (int i = 0; i < 64; i++) m += sA[i];
    m *= (1.f/64.f);
    float v = 0.f;
    for (int i = 0; i < 64; i++) { float d = sA[i] - m; v += d*d; }
    v *= (1.f/64.f);
    float rs = rsqrtf(v + 1e-12f);
    float pr = fmaxf((sA[t] - m)*rs*gp[t] + bep[t], 0.f);
    sB[t] = pr;
    __syncthreads();

    float l = b3[t];
    #pragma unroll 8
    for (int k = 0; k < 64; k++) l += sB[k]*W3[k*64 + t];
    __syncthreads();
    sA[t] = l;
    __syncthreads();

    float mx = -1e30f;
    for (int i = 0; i < 64; i++) mx = fmaxf(mx, sA[i]);
    float den = 0.f, num = 0.f;
    for (int i = 0; i < 64; i++) {
        float e = __expf(sA[i] - mx);
        den += e;
        num += e*xs_s[i];
    }
    if (t == 0) out[q] = num / den;
}

// ---------------------------------------------------------------------------
extern "C" void kernel_launch(void* const* d_in, const int* in_sizes, int n_in,
                              void* d_out, int out_size)
{
    const float* obs  = (const float*)d_in[0];
    const float* act  = (const float*)d_in[1];
    const float* W1   = (const float*)d_in[2];
    const float* b1   = (const float*)d_in[3];
    const float* g1   = (const float*)d_in[4];
    const float* be1  = (const float*)d_in[5];
    const float* W2   = (const float*)d_in[6];
    const float* b2   = (const float*)d_in[7];
    const float* g2   = (const float*)d_in[8];
    const float* be2  = (const float*)d_in[9];
    const float* Wf   = (const float*)d_in[10];
    const float* bf   = (const float*)d_in[11];
    const float* Wb   = (const float*)d_in[12];
    const float* bb   = (const float*)d_in[13];
    const float* wx   = (const float*)d_in[14];
    const float* bx   = (const float*)d_in[15];
    const float* wp   = (const float*)d_in[16];
    const float* bp   = (const float*)d_in[17];
    const float* gp   = (const float*)d_in[18];
    const float* bep  = (const float*)d_in[19];
    const float* W3   = (const float*)d_in[20];
    const float* b3   = (const float*)d_in[21];

    const int trunk_smem = TRUNK_SMEM_F * 4;
    cudaFuncSetAttribute(trunk_kernel,    cudaFuncAttributeMaxDynamicSharedMemorySize, trunk_smem);
    cudaFuncSetAttribute(lstm_mma_kernel, cudaFuncAttributeMaxDynamicSharedMemorySize, LSTM_SMEM_BYTES);

    trunk_kernel<<<NROWS/256, 256, trunk_smem>>>(obs, act, W1, b1, g1, be1,
                                                 W2, b2, g2, be2);
    lstm_mma_kernel<<<dim3(NB/64, 2), 256, LSTM_SMEM_BYTES>>>(Wf, bf, Wb, bb);
    head_kernel<<<2*NB, 64>>>(wx, bx, wp, bp, gp, bep, W3, b3, (float*)d_out);
}